// round 6
// baseline (speedup 1.0000x reference)
#include <cuda_runtime.h>
#include <math.h>
#include <stdint.h>

#define N_NODES 50000
#define N_EDGES 800000
#define IN_DIM  512
#define HID     256
#define LAT     64
#define SLOPE   0.2f

// ---------------- scratch (no allocations allowed) ----------------
__device__ float g_h1 [(size_t)N_NODES * HID];
__device__ float g_h1o[(size_t)N_NODES * HID];
__device__ float g_aggL[(size_t)N_NODES * LAT];   // decoder: aggregated latent
__device__ float g_h3o[(size_t)N_NODES * HID];
__device__ float g_asrc[N_NODES];
__device__ float g_adst[N_NODES];
__device__ float g_inv [N_NODES];      // 1/denominator per dst node
__device__ float g_alpha[N_EDGES];     // UNNORMALIZED exp(leakyrelu(e)), CSR order
__device__ int   g_deg[N_NODES];
__device__ int   g_off[N_NODES + 1];
__device__ int   g_cursor[N_NODES];
__device__ int   g_ssrc[N_EDGES];      // src node per CSR-sorted edge
__device__ int   g_part[64];           // lookback scan: inclusive block totals
__device__ int   g_flag[64];           // lookback scan: ready flags

// ---------------- init: zero counters, attention accumulators, scan flags ----
__global__ void k_zero() {
    int i = blockIdx.x * blockDim.x + threadIdx.x;
    if (i < N_NODES) { g_deg[i] = 0; g_asrc[i] = 0.f; g_adst[i] = 0.f; }
    if (i < 64) g_flag[i] = 0;
}

__global__ void k_count(const int* __restrict__ dst) {
    int e = blockIdx.x * blockDim.x + threadIdx.x;
    if (e < N_EDGES) atomicAdd(&g_deg[dst[e]], 1);
}

// ---------------- single-kernel decoupled-lookback exclusive scan ------------
// 49 blocks (<= 148 SMs, all resident) -> chained wait is deadlock-free.
__global__ void k_scan() {
    __shared__ int buf[1024];
    __shared__ int s_prev;
    int b = blockIdx.x, t = threadIdx.x;
    int idx = b * 1024 + t;
    int v = (idx < N_NODES) ? g_deg[idx] : 0;
    buf[t] = v;
    __syncthreads();
    for (int o = 1; o < 1024; o <<= 1) {
        int x = (t >= o) ? buf[t - o] : 0;
        __syncthreads();
        buf[t] += x;
        __syncthreads();
    }
    if (t == 0) {
        int prev = 0;
        if (b > 0) {
            while (atomicAdd(&g_flag[b - 1], 0) == 0) {}
            __threadfence();
            prev = g_part[b - 1];
        }
        g_part[b] = prev + buf[1023];
        __threadfence();
        atomicExch(&g_flag[b], 1);
        s_prev = prev;
    }
    __syncthreads();
    if (idx < N_NODES) {
        int o = s_prev + buf[t] - v;
        g_off[idx] = o;
        g_cursor[idx] = o;
    }
    if (b == 0 && t == 0) g_off[N_NODES] = N_EDGES;
}

__global__ void k_fill(const int* __restrict__ src, const int* __restrict__ dst) {
    int e = blockIdx.x * blockDim.x + threadIdx.x;
    if (e < N_EDGES) {
        int d = dst[e];
        int p = atomicAdd(&g_cursor[d], 1);
        g_ssrc[p] = src[e];
    }
}

// ---------------- fused segment softmax + aggregation (encoder, ELU) --------
__global__ void k_smax_agg_elu(const float* __restrict__ h, float* __restrict__ out) {
    int w = (blockIdx.x * blockDim.x + threadIdx.x) >> 5;
    int lane = threadIdx.x & 31;
    if (w >= N_NODES) return;
    int lo = g_off[w], hi = g_off[w + 1];

    float4 acc0 = make_float4(0.f, 0.f, 0.f, 0.f);
    float4 acc1 = make_float4(0.f, 0.f, 0.f, 0.f);
    float inv = 0.f;

    if (lo < hi) {
        float ad = g_adst[w];
        float sum = 0.f;
        for (int p = lo + lane; p < hi; p += 32) {
            float e = g_asrc[g_ssrc[p]] + ad;
            e = e > 0.f ? e : SLOPE * e;
            float ex = __expf(e);
            g_alpha[p] = ex;
            sum += ex;
        }
        for (int o = 16; o; o >>= 1) sum += __shfl_xor_sync(0xffffffffu, sum, o);
        inv = 1.f / sum;
        if (lane == 0) g_inv[w] = inv;
        __syncwarp();

        int p = lo;
        int sn = g_ssrc[p];
        float an = g_alpha[p];
        const float4* r = (const float4*)(h + (size_t)sn * HID);
        float4 n0 = r[lane], n1 = r[lane + 32];
        while (p < hi) {
            float a = an;
            float4 v0 = n0, v1 = n1;
            ++p;
            if (p < hi) {
                sn = g_ssrc[p];
                an = g_alpha[p];
                r = (const float4*)(h + (size_t)sn * HID);
                n0 = r[lane]; n1 = r[lane + 32];
            }
            acc0.x += a * v0.x; acc0.y += a * v0.y; acc0.z += a * v0.z; acc0.w += a * v0.w;
            acc1.x += a * v1.x; acc1.y += a * v1.y; acc1.z += a * v1.z; acc1.w += a * v1.w;
        }
    }

    float v[8] = {acc0.x, acc0.y, acc0.z, acc0.w, acc1.x, acc1.y, acc1.z, acc1.w};
#pragma unroll
    for (int i = 0; i < 8; i++) {
        v[i] *= inv;
        v[i] = v[i] > 0.f ? v[i] : (__expf(v[i]) - 1.f);
    }
    float4* o4 = (float4*)(out + (size_t)w * HID);
    o4[lane]      = make_float4(v[0], v[1], v[2], v[3]);
    o4[lane + 32] = make_float4(v[4], v[5], v[6], v[7]);
}

// ---------------- decoder aggregation in LATENT space (64 ch, no act) -------
// aggL[n] = (sum_p alpha[p] * latent[ssrc[p]]) * inv[n]
// (aggregation is linear; the W2^T GEMM and ReLU are applied afterwards)
__global__ void k_agg_lat(const float* __restrict__ latent, float* __restrict__ out) {
    int w = (blockIdx.x * blockDim.x + threadIdx.x) >> 5;
    int lane = threadIdx.x & 31;
    if (w >= N_NODES) return;
    int lo = g_off[w], hi = g_off[w + 1];
    float ax = 0.f, ay = 0.f;
    float inv = 0.f;
    if (lo < hi) {
        inv = g_inv[w];
        int p = lo;
        float an = g_alpha[p];
        const float2* r = (const float2*)(latent + (size_t)g_ssrc[p] * LAT);
        float2 nv = r[lane];
        while (p < hi) {
            float a = an;
            float2 v = nv;
            ++p;
            if (p < hi) {
                an = g_alpha[p];
                r = (const float2*)(latent + (size_t)g_ssrc[p] * LAT);
                nv = r[lane];
            }
            ax += a * v.x; ay += a * v.y;
        }
    }
    ((float2*)(out + (size_t)w * LAT))[lane] = make_float2(ax * inv, ay * inv);
}

// ---------------- TF32 tensor-core GEMM, cp.async double-buffered ----------------
// C[M,N] = A[M,K] @ B ;  B row-major [K,N], or [N,K] when TRANSB (uses B^T).
// BM=128, BN in {64,128}, BK=16, 256 threads (8 warps), warp tile 32 x BN/2.
// EPI: atomicAdd per-row dots with att_src/att_dst into g_asrc/g_adst.
// ACT: 0 none, 1 ReLU on output.

__device__ __forceinline__ uint32_t f2tf32(float x) {
    uint32_t r;
    asm("cvt.rna.tf32.f32 %0, %1;" : "=r"(r) : "f"(x));
    return r;
}

__device__ __forceinline__ void mma_tf32(float* c, const uint32_t* a, const uint32_t* b) {
    asm volatile(
        "mma.sync.aligned.m16n8k8.row.col.f32.tf32.tf32.f32 "
        "{%0,%1,%2,%3}, {%4,%5,%6,%7}, {%8,%9}, {%0,%1,%2,%3};\n"
        : "+f"(c[0]), "+f"(c[1]), "+f"(c[2]), "+f"(c[3])
        : "r"(a[0]), "r"(a[1]), "r"(a[2]), "r"(a[3]), "r"(b[0]), "r"(b[1]));
}

__device__ __forceinline__ void cp_async16(void* dst, const void* src, bool full) {
    uint32_t d = (uint32_t)__cvta_generic_to_shared(dst);
    int sz = full ? 16 : 0;
    asm volatile("cp.async.cg.shared.global [%0], [%1], 16, %2;\n"
                 :: "r"(d), "l"(src), "r"(sz));
}

#define A_LD 20   // 16 + 4 pad: banks 20*gid+tig form a permutation of 0..31

template <bool TRANSB, int BN, bool EPI, int ACT>
__global__ __launch_bounds__(256, 2)
void gemm_tf32(const float* __restrict__ A, const float* __restrict__ B,
               float* __restrict__ C, int M, int N, int K,
               const float* __restrict__ attS, const float* __restrict__ attD) {
    constexpr int NF  = BN / 16;
    constexpr int BLD = BN + 8;
    constexpr int BSZ = TRANSB ? BN * A_LD : 16 * BLD;
    __shared__ float As[2][128][A_LD];
    __shared__ float Bs[2][BSZ];

    const int t    = threadIdx.x;
    const int lane = t & 31;
    const int warp = t >> 5;
    const int wm   = warp >> 1;
    const int wn   = warp & 1;
    const int gid  = lane >> 2;
    const int tig  = lane & 3;

    const int mb = blockIdx.y * 128;
    const int nb = blockIdx.x * BN;

    float acc[2][NF][4];
#pragma unroll
    for (int i = 0; i < 2; i++)
#pragma unroll
        for (int j = 0; j < NF; j++)
#pragma unroll
            for (int r = 0; r < 4; r++) acc[i][j][r] = 0.f;

    auto load_tile = [&](int s, int k0) {
#pragma unroll
        for (int h = 0; h < 2; h++) {
            int idx = t + h * 256;
            int row = idx >> 2;
            int kq  = (idx & 3) * 4;
            cp_async16(&As[s][row][kq],
                       A + (size_t)(mb + row) * K + k0 + kq,
                       (mb + row) < M);
        }
        if (!TRANSB) {
#pragma unroll
            for (int h = 0; h < BN / 64; h++) {
                int idx = t + h * 256;
                int kk  = idx / (BN / 4);
                int nn  = (idx % (BN / 4)) * 4;
                cp_async16(&Bs[s][kk * BLD + nn],
                           B + (size_t)(k0 + kk) * N + nb + nn, true);
            }
        } else {
#pragma unroll
            for (int h = 0; h < BN / 64; h++) {
                int idx = t + h * 256;
                int nn  = idx >> 2;
                int kq  = (idx & 3) * 4;
                cp_async16(&Bs[s][nn * A_LD + kq],
                           B + (size_t)(nb + nn) * K + k0 + kq, true);
            }
        }
        asm volatile("cp.async.commit_group;\n" ::: "memory");
    };

    const int KT = K >> 4;
    load_tile(0, 0);

    for (int kt = 0; kt < KT; kt++) {
        const int s = kt & 1;
        if (kt + 1 < KT) {
            load_tile(s ^ 1, (kt + 1) << 4);
            asm volatile("cp.async.wait_group 1;\n" ::: "memory");
        } else {
            asm volatile("cp.async.wait_group 0;\n" ::: "memory");
        }
        __syncthreads();

#pragma unroll
        for (int kc = 0; kc < 16; kc += 8) {
            uint32_t af[2][4], bf[NF][2];
#pragma unroll
            for (int i = 0; i < 2; i++) {
                int row = wm * 32 + i * 16 + gid;
                af[i][0] = f2tf32(As[s][row][kc + tig]);
                af[i][1] = f2tf32(As[s][row + 8][kc + tig]);
                af[i][2] = f2tf32(As[s][row][kc + tig + 4]);
                af[i][3] = f2tf32(As[s][row + 8][kc + tig + 4]);
            }
#pragma unroll
            for (int j = 0; j < NF; j++) {
                int col = wn * (BN / 2) + j * 8 + gid;
                if (!TRANSB) {
                    bf[j][0] = f2tf32(Bs[s][(kc + tig) * BLD + col]);
                    bf[j][1] = f2tf32(Bs[s][(kc + tig + 4) * BLD + col]);
                } else {
                    bf[j][0] = f2tf32(Bs[s][col * A_LD + kc + tig]);
                    bf[j][1] = f2tf32(Bs[s][col * A_LD + kc + tig + 4]);
                }
            }
#pragma unroll
            for (int i = 0; i < 2; i++)
#pragma unroll
                for (int j = 0; j < NF; j++)
                    mma_tf32(acc[i][j], af[i], bf[j]);
        }
        __syncthreads();
    }

    if (ACT == 1) {
#pragma unroll
        for (int i = 0; i < 2; i++)
#pragma unroll
            for (int j = 0; j < NF; j++)
#pragma unroll
                for (int r = 0; r < 4; r++)
                    acc[i][j][r] = acc[i][j][r] > 0.f ? acc[i][j][r] : 0.f;
    }

#pragma unroll
    for (int i = 0; i < 2; i++) {
        int r0 = mb + wm * 32 + i * 16 + gid;
#pragma unroll
        for (int j = 0; j < NF; j++) {
            int c0 = nb + wn * (BN / 2) + j * 8 + tig * 2;
            if (r0 < M)
                *(float2*)(C + (size_t)r0 * N + c0) = make_float2(acc[i][j][0], acc[i][j][1]);
            if (r0 + 8 < M)
                *(float2*)(C + (size_t)(r0 + 8) * N + c0) = make_float2(acc[i][j][2], acc[i][j][3]);
        }
    }

    if (EPI) {
#pragma unroll
        for (int i = 0; i < 2; i++) {
            float ps = 0.f, pd = 0.f, ps8 = 0.f, pd8 = 0.f;
#pragma unroll
            for (int j = 0; j < NF; j++) {
                int c0 = nb + wn * (BN / 2) + j * 8 + tig * 2;
                float sa = __ldg(attS + c0), sb = __ldg(attS + c0 + 1);
                float da = __ldg(attD + c0), db = __ldg(attD + c0 + 1);
                ps  += acc[i][j][0] * sa + acc[i][j][1] * sb;
                pd  += acc[i][j][0] * da + acc[i][j][1] * db;
                ps8 += acc[i][j][2] * sa + acc[i][j][3] * sb;
                pd8 += acc[i][j][2] * da + acc[i][j][3] * db;
            }
#pragma unroll
            for (int o = 1; o <= 2; o <<= 1) {
                ps  += __shfl_xor_sync(0xffffffffu, ps,  o);
                pd  += __shfl_xor_sync(0xffffffffu, pd,  o);
                ps8 += __shfl_xor_sync(0xffffffffu, ps8, o);
                pd8 += __shfl_xor_sync(0xffffffffu, pd8, o);
            }
            if (tig == 0) {
                int r0 = mb + wm * 32 + i * 16 + gid;
                if (r0 < M)     { atomicAdd(&g_asrc[r0], ps);      atomicAdd(&g_adst[r0], pd); }
                if (r0 + 8 < M) { atomicAdd(&g_asrc[r0 + 8], ps8); atomicAdd(&g_adst[r0 + 8], pd8); }
            }
        }
    }
}

// ---------------- launch ----------------
extern "C" void kernel_launch(void* const* d_in, const int* in_sizes, int n_in,
                              void* d_out, int out_size) {
    const float* x        = (const float*)d_in[0];
    const int*   ei       = (const int*)d_in[1];
    const float* W1       = (const float*)d_in[2];
    const float* W2       = (const float*)d_in[3];
    const float* att_src1 = (const float*)d_in[4];
    const float* att_dst1 = (const float*)d_in[5];

    float* latent = (float*)d_out;                               // [N, LAT]
    float* recon  = latent + (size_t)N_NODES * LAT;              // [N, IN_DIM]
    const int* src = ei;
    const int* dst = ei + N_EDGES;

    float *h1, *h1o, *aggL, *h3o;
    cudaGetSymbolAddress((void**)&h1,   g_h1);
    cudaGetSymbolAddress((void**)&h1o,  g_h1o);
    cudaGetSymbolAddress((void**)&aggL, g_aggL);
    cudaGetSymbolAddress((void**)&h3o,  g_h3o);

    const int EB = (N_EDGES + 255) / 256;
    const int NB = (N_NODES + 255) / 256;
    const int WB = (N_NODES * 32 + 255) / 256;   // warp-per-node kernels
    const int MT = (N_NODES + 127) / 128;        // gemm M tiles
    const int SB = (N_NODES + 1023) / 1024;      // scan blocks (49)

    // init (zeroes deg, asrc/adst accumulators, scan flags)
    k_zero<<<NB, 256>>>();

    // encoder GAT1 GEMM first (independent of CSR): h1 = x @ W1 + fused att dots
    gemm_tf32<false, 128, true, 0><<<dim3(HID / 128, MT), 256>>>(
        x, W1, h1, N_NODES, HID, IN_DIM, att_src1, att_dst1);

    // CSR build
    k_count<<<EB, 256>>>(dst);
    k_scan<<<SB, 1024>>>();
    k_fill<<<EB, 256>>>(src, dst);

    // encoder edge phase: fused softmax + aggregation (ELU)
    k_smax_agg_elu<<<WB, 256>>>(h1, h1o);

    // encoder GAT2: latent = h1o @ W2
    gemm_tf32<false, 64, false, 0><<<dim3(LAT / 64, MT), 256>>>(
        h1o, W2, latent, N_NODES, LAT, HID, nullptr, nullptr);

    // decoder GAT1 (restructured): aggregate latent, then h3o = relu(aggL @ W2^T)
    k_agg_lat<<<WB, 256>>>(latent, aggL);
    gemm_tf32<true, 128, false, 1><<<dim3(HID / 128, MT), 256>>>(
        aggL, W2, h3o, N_NODES, HID, LAT, nullptr, nullptr);

    // decoder GAT2: recon = h3o @ W1^T
    gemm_tf32<true, 128, false, 0><<<dim3(IN_DIM / 128, MT), 256>>>(
        h3o, W1, recon, N_NODES, IN_DIM, HID, nullptr, nullptr);
}

// round 10
// speedup vs baseline: 1.1597x; 1.1597x over previous
#include <cuda_runtime.h>
#include <math.h>
#include <stdint.h>

#define N_NODES 50000
#define N_EDGES 800000
#define IN_DIM  512
#define HID     256
#define LAT     64
#define SLOPE   0.2f

// ---------------- scratch (no allocations allowed) ----------------
__device__ float g_h1 [(size_t)N_NODES * HID];
__device__ float g_h1o[(size_t)N_NODES * HID];
__device__ float g_aggL[(size_t)N_NODES * LAT];   // decoder: aggregated latent
__device__ float g_h3o[(size_t)N_NODES * HID];
__device__ float g_asrc[N_NODES];
__device__ float g_adst[N_NODES];
__device__ float g_inv [N_NODES];      // 1/denominator per dst node
__device__ float g_alpha[N_EDGES];     // UNNORMALIZED exp(leakyrelu(e)), CSR order
__device__ int   g_deg[N_NODES];
__device__ int   g_off[N_NODES + 1];
__device__ int   g_cursor[N_NODES];
__device__ int   g_ssrc[N_EDGES];      // src node per CSR-sorted edge
__device__ int   g_bsum[64];           // block sums for 3-kernel scan

// ---------------- init ----------------
__global__ void k_zero() {
    int i = blockIdx.x * blockDim.x + threadIdx.x;
    if (i < N_NODES) { g_deg[i] = 0; g_asrc[i] = 0.f; g_adst[i] = 0.f; }
}

__global__ void k_count(const int* __restrict__ dst) {
    int e = blockIdx.x * blockDim.x + threadIdx.x;
    if (e < N_EDGES) atomicAdd(&g_deg[dst[e]], 1);
}

// ---------------- 3-kernel scan (parallel, launch-cheap) ----------------
// scan1: per-block inclusive scan (warp-shuffle based), block totals -> g_bsum
__global__ void k_scan1() {
    __shared__ int wsum[32];
    int b = blockIdx.x, t = threadIdx.x;
    int lane = t & 31, wid = t >> 5;
    int idx = b * 1024 + t;
    int v = (idx < N_NODES) ? g_deg[idx] : 0;
    int x = v;
#pragma unroll
    for (int o = 1; o < 32; o <<= 1) {
        int y = __shfl_up_sync(0xffffffffu, x, o);
        if (lane >= o) x += y;
    }
    if (lane == 31) wsum[wid] = x;
    __syncthreads();
    if (wid == 0) {
        int w = wsum[lane];
#pragma unroll
        for (int o = 1; o < 32; o <<= 1) {
            int y = __shfl_up_sync(0xffffffffu, w, o);
            if (lane >= o) w += y;
        }
        wsum[lane] = w;
    }
    __syncthreads();
    int incl = x + (wid ? wsum[wid - 1] : 0);
    if (idx < N_NODES) g_off[idx] = incl - v;          // block-local exclusive
    if (t == 1023) g_bsum[b] = incl;
}

// scan2: exclusive scan of block sums (<= 64 blocks)
__global__ void k_scan2(int nblocks) {
    int t = threadIdx.x;
    int v = (t < nblocks) ? g_bsum[t] : 0;
    int x = v;
#pragma unroll
    for (int o = 1; o < 32; o <<= 1) {
        int y = __shfl_up_sync(0xffffffffu, x, o);
        if ((t & 31) >= o) x += y;
    }
    __shared__ int w0;
    if (t == 31) w0 = x;
    __syncthreads();
    int incl = x + ((t >= 32) ? w0 : 0);
    g_bsum[t] = incl - v;
}

__global__ void k_scan3() {
    int i = blockIdx.x * blockDim.x + threadIdx.x;
    if (i < N_NODES) {
        int o = g_off[i] + g_bsum[i >> 10];
        g_off[i] = o;
        g_cursor[i] = o;
    }
    if (i == 0) g_off[N_NODES] = N_EDGES;
}

__global__ void k_fill(const int* __restrict__ src, const int* __restrict__ dst) {
    int e = blockIdx.x * blockDim.x + threadIdx.x;
    if (e < N_EDGES) {
        int d = dst[e];
        int p = atomicAdd(&g_cursor[d], 1);
        g_ssrc[p] = src[e];
    }
}

// ---------------- fused segment softmax + aggregation (encoder, ELU) --------
__global__ void k_smax_agg_elu(const float* __restrict__ h, float* __restrict__ out) {
    int w = (blockIdx.x * blockDim.x + threadIdx.x) >> 5;
    int lane = threadIdx.x & 31;
    if (w >= N_NODES) return;
    int lo = g_off[w], hi = g_off[w + 1];

    float4 acc0 = make_float4(0.f, 0.f, 0.f, 0.f);
    float4 acc1 = make_float4(0.f, 0.f, 0.f, 0.f);
    float inv = 0.f;

    if (lo < hi) {
        float ad = g_adst[w];
        float sum = 0.f;
        for (int p = lo + lane; p < hi; p += 32) {
            float e = g_asrc[g_ssrc[p]] + ad;
            e = e > 0.f ? e : SLOPE * e;
            float ex = __expf(e);
            g_alpha[p] = ex;
            sum += ex;
        }
        for (int o = 16; o; o >>= 1) sum += __shfl_xor_sync(0xffffffffu, sum, o);
        inv = 1.f / sum;
        if (lane == 0) g_inv[w] = inv;
        __syncwarp();

        int p = lo;
        int sn = g_ssrc[p];
        float an = g_alpha[p];
        const float4* r = (const float4*)(h + (size_t)sn * HID);
        float4 n0 = r[lane], n1 = r[lane + 32];
        while (p < hi) {
            float a = an;
            float4 v0 = n0, v1 = n1;
            ++p;
            if (p < hi) {
                sn = g_ssrc[p];
                an = g_alpha[p];
                r = (const float4*)(h + (size_t)sn * HID);
                n0 = r[lane]; n1 = r[lane + 32];
            }
            acc0.x += a * v0.x; acc0.y += a * v0.y; acc0.z += a * v0.z; acc0.w += a * v0.w;
            acc1.x += a * v1.x; acc1.y += a * v1.y; acc1.z += a * v1.z; acc1.w += a * v1.w;
        }
    }

    float v[8] = {acc0.x, acc0.y, acc0.z, acc0.w, acc1.x, acc1.y, acc1.z, acc1.w};
#pragma unroll
    for (int i = 0; i < 8; i++) {
        v[i] *= inv;
        v[i] = v[i] > 0.f ? v[i] : (__expf(v[i]) - 1.f);
    }
    float4* o4 = (float4*)(out + (size_t)w * HID);
    o4[lane]      = make_float4(v[0], v[1], v[2], v[3]);
    o4[lane + 32] = make_float4(v[4], v[5], v[6], v[7]);
}

// ---------------- decoder aggregation in LATENT space (64 ch, no act) -------
// aggL[n] = (sum_p alpha[p] * latent[ssrc[p]]) * inv[n]
__global__ void k_agg_lat(const float* __restrict__ latent, float* __restrict__ out) {
    int w = (blockIdx.x * blockDim.x + threadIdx.x) >> 5;
    int lane = threadIdx.x & 31;
    if (w >= N_NODES) return;
    int lo = g_off[w], hi = g_off[w + 1];
    float ax = 0.f, ay = 0.f;
    float inv = 0.f;
    if (lo < hi) {
        inv = g_inv[w];
        int p = lo;
        float an = g_alpha[p];
        const float2* r = (const float2*)(latent + (size_t)g_ssrc[p] * LAT);
        float2 nv = r[lane];
        while (p < hi) {
            float a = an;
            float2 v = nv;
            ++p;
            if (p < hi) {
                an = g_alpha[p];
                r = (const float2*)(latent + (size_t)g_ssrc[p] * LAT);
                nv = r[lane];
            }
            ax += a * v.x; ay += a * v.y;
        }
    }
    ((float2*)(out + (size_t)w * LAT))[lane] = make_float2(ax * inv, ay * inv);
}

// ---------------- TF32 tensor-core GEMM, cp.async double-buffered ----------------
__device__ __forceinline__ uint32_t f2tf32(float x) {
    uint32_t r;
    asm("cvt.rna.tf32.f32 %0, %1;" : "=r"(r) : "f"(x));
    return r;
}

__device__ __forceinline__ void mma_tf32(float* c, const uint32_t* a, const uint32_t* b) {
    asm volatile(
        "mma.sync.aligned.m16n8k8.row.col.f32.tf32.tf32.f32 "
        "{%0,%1,%2,%3}, {%4,%5,%6,%7}, {%8,%9}, {%0,%1,%2,%3};\n"
        : "+f"(c[0]), "+f"(c[1]), "+f"(c[2]), "+f"(c[3])
        : "r"(a[0]), "r"(a[1]), "r"(a[2]), "r"(a[3]), "r"(b[0]), "r"(b[1]));
}

__device__ __forceinline__ void cp_async16(void* dst, const void* src, bool full) {
    uint32_t d = (uint32_t)__cvta_generic_to_shared(dst);
    int sz = full ? 16 : 0;
    asm volatile("cp.async.cg.shared.global [%0], [%1], 16, %2;\n"
                 :: "r"(d), "l"(src), "r"(sz));
}

#define A_LD 20   // 16 + 4 pad: banks 20*gid+tig form a permutation of 0..31

template <bool TRANSB, int BN, bool EPI, int ACT>
__global__ __launch_bounds__(256, 2)
void gemm_tf32(const float* __restrict__ A, const float* __restrict__ B,
               float* __restrict__ C, int M, int N, int K,
               const float* __restrict__ attS, const float* __restrict__ attD) {
    constexpr int NF  = BN / 16;
    constexpr int BLD = BN + 8;
    constexpr int BSZ = TRANSB ? BN * A_LD : 16 * BLD;
    __shared__ float As[2][128][A_LD];
    __shared__ float Bs[2][BSZ];

    const int t    = threadIdx.x;
    const int lane = t & 31;
    const int warp = t >> 5;
    const int wm   = warp >> 1;
    const int wn   = warp & 1;
    const int gid  = lane >> 2;
    const int tig  = lane & 3;

    const int mb = blockIdx.y * 128;
    const int nb = blockIdx.x * BN;

    float acc[2][NF][4];
#pragma unroll
    for (int i = 0; i < 2; i++)
#pragma unroll
        for (int j = 0; j < NF; j++)
#pragma unroll
            for (int r = 0; r < 4; r++) acc[i][j][r] = 0.f;

    auto load_tile = [&](int s, int k0) {
#pragma unroll
        for (int h = 0; h < 2; h++) {
            int idx = t + h * 256;
            int row = idx >> 2;
            int kq  = (idx & 3) * 4;
            cp_async16(&As[s][row][kq],
                       A + (size_t)(mb + row) * K + k0 + kq,
                       (mb + row) < M);
        }
        if (!TRANSB) {
#pragma unroll
            for (int h = 0; h < BN / 64; h++) {
                int idx = t + h * 256;
                int kk  = idx / (BN / 4);
                int nn  = (idx % (BN / 4)) * 4;
                cp_async16(&Bs[s][kk * BLD + nn],
                           B + (size_t)(k0 + kk) * N + nb + nn, true);
            }
        } else {
#pragma unroll
            for (int h = 0; h < BN / 64; h++) {
                int idx = t + h * 256;
                int nn  = idx >> 2;
                int kq  = (idx & 3) * 4;
                cp_async16(&Bs[s][nn * A_LD + kq],
                           B + (size_t)(nb + nn) * K + k0 + kq, true);
            }
        }
        asm volatile("cp.async.commit_group;\n" ::: "memory");
    };

    const int KT = K >> 4;
    load_tile(0, 0);

    for (int kt = 0; kt < KT; kt++) {
        const int s = kt & 1;
        if (kt + 1 < KT) {
            load_tile(s ^ 1, (kt + 1) << 4);
            asm volatile("cp.async.wait_group 1;\n" ::: "memory");
        } else {
            asm volatile("cp.async.wait_group 0;\n" ::: "memory");
        }
        __syncthreads();

#pragma unroll
        for (int kc = 0; kc < 16; kc += 8) {
            uint32_t af[2][4], bf[NF][2];
#pragma unroll
            for (int i = 0; i < 2; i++) {
                int row = wm * 32 + i * 16 + gid;
                af[i][0] = f2tf32(As[s][row][kc + tig]);
                af[i][1] = f2tf32(As[s][row + 8][kc + tig]);
                af[i][2] = f2tf32(As[s][row][kc + tig + 4]);
                af[i][3] = f2tf32(As[s][row + 8][kc + tig + 4]);
            }
#pragma unroll
            for (int j = 0; j < NF; j++) {
                int col = wn * (BN / 2) + j * 8 + gid;
                if (!TRANSB) {
                    bf[j][0] = f2tf32(Bs[s][(kc + tig) * BLD + col]);
                    bf[j][1] = f2tf32(Bs[s][(kc + tig + 4) * BLD + col]);
                } else {
                    bf[j][0] = f2tf32(Bs[s][col * A_LD + kc + tig]);
                    bf[j][1] = f2tf32(Bs[s][col * A_LD + kc + tig + 4]);
                }
            }
#pragma unroll
            for (int i = 0; i < 2; i++)
#pragma unroll
                for (int j = 0; j < NF; j++)
                    mma_tf32(acc[i][j], af[i], bf[j]);
        }
        __syncthreads();
    }

    if (ACT == 1) {
#pragma unroll
        for (int i = 0; i < 2; i++)
#pragma unroll
            for (int j = 0; j < NF; j++)
#pragma unroll
                for (int r = 0; r < 4; r++)
                    acc[i][j][r] = acc[i][j][r] > 0.f ? acc[i][j][r] : 0.f;
    }

#pragma unroll
    for (int i = 0; i < 2; i++) {
        int r0 = mb + wm * 32 + i * 16 + gid;
#pragma unroll
        for (int j = 0; j < NF; j++) {
            int c0 = nb + wn * (BN / 2) + j * 8 + tig * 2;
            if (r0 < M)
                *(float2*)(C + (size_t)r0 * N + c0) = make_float2(acc[i][j][0], acc[i][j][1]);
            if (r0 + 8 < M)
                *(float2*)(C + (size_t)(r0 + 8) * N + c0) = make_float2(acc[i][j][2], acc[i][j][3]);
        }
    }

    if (EPI) {
#pragma unroll
        for (int i = 0; i < 2; i++) {
            float ps = 0.f, pd = 0.f, ps8 = 0.f, pd8 = 0.f;
#pragma unroll
            for (int j = 0; j < NF; j++) {
                int c0 = nb + wn * (BN / 2) + j * 8 + tig * 2;
                float sa = __ldg(attS + c0), sb = __ldg(attS + c0 + 1);
                float da = __ldg(attD + c0), db = __ldg(attD + c0 + 1);
                ps  += acc[i][j][0] * sa + acc[i][j][1] * sb;
                pd  += acc[i][j][0] * da + acc[i][j][1] * db;
                ps8 += acc[i][j][2] * sa + acc[i][j][3] * sb;
                pd8 += acc[i][j][2] * da + acc[i][j][3] * db;
            }
#pragma unroll
            for (int o = 1; o <= 2; o <<= 1) {
                ps  += __shfl_xor_sync(0xffffffffu, ps,  o);
                pd  += __shfl_xor_sync(0xffffffffu, pd,  o);
                ps8 += __shfl_xor_sync(0xffffffffu, ps8, o);
                pd8 += __shfl_xor_sync(0xffffffffu, pd8, o);
            }
            if (tig == 0) {
                int r0 = mb + wm * 32 + i * 16 + gid;
                if (r0 < M)     { atomicAdd(&g_asrc[r0], ps);      atomicAdd(&g_adst[r0], pd); }
                if (r0 + 8 < M) { atomicAdd(&g_asrc[r0 + 8], ps8); atomicAdd(&g_adst[r0 + 8], pd8); }
            }
        }
    }
}

// ---------------- launch ----------------
extern "C" void kernel_launch(void* const* d_in, const int* in_sizes, int n_in,
                              void* d_out, int out_size) {
    const float* x        = (const float*)d_in[0];
    const int*   ei       = (const int*)d_in[1];
    const float* W1       = (const float*)d_in[2];
    const float* W2       = (const float*)d_in[3];
    const float* att_src1 = (const float*)d_in[4];
    const float* att_dst1 = (const float*)d_in[5];

    float* latent = (float*)d_out;                               // [N, LAT]
    float* recon  = latent + (size_t)N_NODES * LAT;              // [N, IN_DIM]
    const int* src = ei;
    const int* dst = ei + N_EDGES;

    float *h1, *h1o, *aggL, *h3o;
    cudaGetSymbolAddress((void**)&h1,   g_h1);
    cudaGetSymbolAddress((void**)&h1o,  g_h1o);
    cudaGetSymbolAddress((void**)&aggL, g_aggL);
    cudaGetSymbolAddress((void**)&h3o,  g_h3o);

    const int EB = (N_EDGES + 255) / 256;
    const int NB = (N_NODES + 255) / 256;
    const int WB = (N_NODES * 32 + 255) / 256;   // warp-per-node kernels
    const int MT = (N_NODES + 127) / 128;        // gemm M tiles
    const int SB = (N_NODES + 1023) / 1024;      // scan blocks (49)

    // init (zeroes deg + att-dot accumulators)
    k_zero<<<NB, 256>>>();

    // encoder GAT1 GEMM (independent of CSR): h1 = x @ W1 + fused att dots
    gemm_tf32<false, 128, true, 0><<<dim3(HID / 128, MT), 256>>>(
        x, W1, h1, N_NODES, HID, IN_DIM, att_src1, att_dst1);

    // CSR build (3-kernel parallel scan)
    k_count<<<EB, 256>>>(dst);
    k_scan1<<<SB, 1024>>>();
    k_scan2<<<1, 64>>>(SB);
    k_scan3<<<NB, 256>>>();
    k_fill<<<EB, 256>>>(src, dst);

    // encoder edge phase: fused softmax + aggregation (ELU)
    k_smax_agg_elu<<<WB, 256>>>(h1, h1o);

    // encoder GAT2: latent = h1o @ W2
    gemm_tf32<false, 64, false, 0><<<dim3(LAT / 64, MT), 256>>>(
        h1o, W2, latent, N_NODES, LAT, HID, nullptr, nullptr);

    // decoder GAT1 (restructured): aggregate latent, then h3o = relu(aggL @ W2^T)
    k_agg_lat<<<WB, 256>>>(latent, aggL);
    gemm_tf32<true, 128, false, 1><<<dim3(HID / 128, MT), 256>>>(
        aggL, W2, h3o, N_NODES, HID, LAT, nullptr, nullptr);

    // decoder GAT2: recon = h3o @ W1^T
    gemm_tf32<true, 128, false, 0><<<dim3(IN_DIM / 128, MT), 256>>>(
        h3o, W1, recon, N_NODES, IN_DIM, HID, nullptr, nullptr);
}

// round 12
// speedup vs baseline: 1.1833x; 1.0204x over previous
#include <cuda_runtime.h>
#include <math.h>
#include <stdint.h>

#define N_NODES 50000
#define N_EDGES 800000
#define IN_DIM  512
#define HID     256
#define LAT     64
#define SLOPE   0.2f

// ---------------- scratch (no allocations allowed) ----------------
__device__ float g_h1 [(size_t)N_NODES * HID];
__device__ float g_h1o[(size_t)N_NODES * HID];
__device__ float g_aggL[(size_t)N_NODES * LAT];   // decoder: aggregated latent
__device__ float g_h3o[(size_t)N_NODES * HID];
__device__ float g_asrc[N_NODES];
__device__ float g_adst[N_NODES];
__device__ float g_inv [N_NODES];      // 1/denominator per dst node
__device__ float g_alpha[N_EDGES];     // UNNORMALIZED exp(leakyrelu(e)), CSR order
__device__ int   g_deg[N_NODES];
__device__ int   g_off[N_NODES + 1];
__device__ int   g_cursor[N_NODES];
__device__ int   g_ssrc[N_EDGES];      // src node per CSR-sorted edge
__device__ int   g_bsum[64];           // block sums for 3-kernel scan

// ---------------- init ----------------
__global__ void k_zero() {
    int i = blockIdx.x * blockDim.x + threadIdx.x;
    if (i < N_NODES) { g_deg[i] = 0; g_asrc[i] = 0.f; g_adst[i] = 0.f; }
}

__global__ void k_count(const int* __restrict__ dst) {
    int e = blockIdx.x * blockDim.x + threadIdx.x;
    if (e < N_EDGES) atomicAdd(&g_deg[dst[e]], 1);
}

// ---------------- 3-kernel scan (parallel, launch-cheap) ----------------
__global__ void k_scan1() {
    __shared__ int wsum[32];
    int b = blockIdx.x, t = threadIdx.x;
    int lane = t & 31, wid = t >> 5;
    int idx = b * 1024 + t;
    int v = (idx < N_NODES) ? g_deg[idx] : 0;
    int x = v;
#pragma unroll
    for (int o = 1; o < 32; o <<= 1) {
        int y = __shfl_up_sync(0xffffffffu, x, o);
        if (lane >= o) x += y;
    }
    if (lane == 31) wsum[wid] = x;
    __syncthreads();
    if (wid == 0) {
        int w = wsum[lane];
#pragma unroll
        for (int o = 1; o < 32; o <<= 1) {
            int y = __shfl_up_sync(0xffffffffu, w, o);
            if (lane >= o) w += y;
        }
        wsum[lane] = w;
    }
    __syncthreads();
    int incl = x + (wid ? wsum[wid - 1] : 0);
    if (idx < N_NODES) g_off[idx] = incl - v;          // block-local exclusive
    if (t == 1023) g_bsum[b] = incl;
}

__global__ void k_scan2(int nblocks) {
    int t = threadIdx.x;
    int v = (t < nblocks) ? g_bsum[t] : 0;
    int x = v;
#pragma unroll
    for (int o = 1; o < 32; o <<= 1) {
        int y = __shfl_up_sync(0xffffffffu, x, o);
        if ((t & 31) >= o) x += y;
    }
    __shared__ int w0;
    if (t == 31) w0 = x;
    __syncthreads();
    int incl = x + ((t >= 32) ? w0 : 0);
    g_bsum[t] = incl - v;
}

__global__ void k_scan3() {
    int i = blockIdx.x * blockDim.x + threadIdx.x;
    if (i < N_NODES) {
        int o = g_off[i] + g_bsum[i >> 10];
        g_off[i] = o;
        g_cursor[i] = o;
    }
    if (i == 0) g_off[N_NODES] = N_EDGES;
}

__global__ void k_fill(const int* __restrict__ src, const int* __restrict__ dst) {
    int e = blockIdx.x * blockDim.x + threadIdx.x;
    if (e < N_EDGES) {
        int d = dst[e];
        int p = atomicAdd(&g_cursor[d], 1);
        g_ssrc[p] = src[e];
    }
}

// ---------------- fused segment softmax + aggregation (encoder, ELU) --------
// Pass A: unnormalized exp -> g_alpha, warp-reduced sum -> g_inv.
// Pass B: depth-2 software-pipelined gather (2 rows = 4 float4 loads in flight).
__global__ void k_smax_agg_elu(const float* __restrict__ h, float* __restrict__ out) {
    int w = (blockIdx.x * blockDim.x + threadIdx.x) >> 5;
    int lane = threadIdx.x & 31;
    if (w >= N_NODES) return;
    int lo = g_off[w], hi = g_off[w + 1];

    float4 acc0 = make_float4(0.f, 0.f, 0.f, 0.f);
    float4 acc1 = make_float4(0.f, 0.f, 0.f, 0.f);
    float inv = 0.f;

    if (lo < hi) {
        float ad = g_adst[w];
        float sum = 0.f;
        for (int p = lo + lane; p < hi; p += 32) {
            float e = g_asrc[g_ssrc[p]] + ad;
            e = e > 0.f ? e : SLOPE * e;
            float ex = __expf(e);
            g_alpha[p] = ex;
            sum += ex;
        }
        for (int o = 16; o; o >>= 1) sum += __shfl_xor_sync(0xffffffffu, sum, o);
        inv = 1.f / sum;
        if (lane == 0) g_inv[w] = inv;
        __syncwarp();

        // depth-2 pipelined gather
        float4 c0, c1, n0, n1;
        float ac, an = 0.f;
        {
            const float4* r = (const float4*)(h + (size_t)g_ssrc[lo] * HID);
            c0 = r[lane]; c1 = r[lane + 32];
            ac = g_alpha[lo];
        }
        n0 = c0; n1 = c1;
        if (lo + 1 < hi) {
            const float4* r = (const float4*)(h + (size_t)g_ssrc[lo + 1] * HID);
            n0 = r[lane]; n1 = r[lane + 32];
            an = g_alpha[lo + 1];
        }
        for (int p = lo; p < hi; ++p) {
            float a = ac;
            float4 v0 = c0, v1 = c1;
            c0 = n0; c1 = n1; ac = an;
            int q = p + 2;
            if (q < hi) {
                const float4* r = (const float4*)(h + (size_t)g_ssrc[q] * HID);
                n0 = r[lane]; n1 = r[lane + 32];
                an = g_alpha[q];
            }
            acc0.x += a * v0.x; acc0.y += a * v0.y; acc0.z += a * v0.z; acc0.w += a * v0.w;
            acc1.x += a * v1.x; acc1.y += a * v1.y; acc1.z += a * v1.z; acc1.w += a * v1.w;
        }
    }

    float v[8] = {acc0.x, acc0.y, acc0.z, acc0.w, acc1.x, acc1.y, acc1.z, acc1.w};
#pragma unroll
    for (int i = 0; i < 8; i++) {
        v[i] *= inv;
        v[i] = v[i] > 0.f ? v[i] : (__expf(v[i]) - 1.f);
    }
    float4* o4 = (float4*)(out + (size_t)w * HID);
    o4[lane]      = make_float4(v[0], v[1], v[2], v[3]);
    o4[lane + 32] = make_float4(v[4], v[5], v[6], v[7]);
}

// ---------------- decoder aggregation in LATENT space (64 ch, no act) -------
// aggL[n] = (sum_p alpha[p] * latent[ssrc[p]]) * inv[n]; depth-2 pipelined.
__global__ void k_agg_lat(const float* __restrict__ latent, float* __restrict__ out) {
    int w = (blockIdx.x * blockDim.x + threadIdx.x) >> 5;
    int lane = threadIdx.x & 31;
    if (w >= N_NODES) return;
    int lo = g_off[w], hi = g_off[w + 1];
    float ax = 0.f, ay = 0.f;
    float inv = 0.f;
    if (lo < hi) {
        inv = g_inv[w];
        float2 cv, nv;
        float ac, an = 0.f;
        {
            const float2* r = (const float2*)(latent + (size_t)g_ssrc[lo] * LAT);
            cv = r[lane];
            ac = g_alpha[lo];
        }
        nv = cv;
        if (lo + 1 < hi) {
            const float2* r = (const float2*)(latent + (size_t)g_ssrc[lo + 1] * LAT);
            nv = r[lane];
            an = g_alpha[lo + 1];
        }
        for (int p = lo; p < hi; ++p) {
            float a = ac;
            float2 v = cv;
            cv = nv; ac = an;
            int q = p + 2;
            if (q < hi) {
                const float2* r = (const float2*)(latent + (size_t)g_ssrc[q] * LAT);
                nv = r[lane];
                an = g_alpha[q];
            }
            ax += a * v.x; ay += a * v.y;
        }
    }
    ((float2*)(out + (size_t)w * LAT))[lane] = make_float2(ax * inv, ay * inv);
}

// ---------------- TF32 tensor-core GEMM, cp.async double-buffered ----------------
__device__ __forceinline__ uint32_t f2tf32(float x) {
    uint32_t r;
    asm("cvt.rna.tf32.f32 %0, %1;" : "=r"(r) : "f"(x));
    return r;
}

__device__ __forceinline__ void mma_tf32(float* c, const uint32_t* a, const uint32_t* b) {
    asm volatile(
        "mma.sync.aligned.m16n8k8.row.col.f32.tf32.tf32.f32 "
        "{%0,%1,%2,%3}, {%4,%5,%6,%7}, {%8,%9}, {%0,%1,%2,%3};\n"
        : "+f"(c[0]), "+f"(c[1]), "+f"(c[2]), "+f"(c[3])
        : "r"(a[0]), "r"(a[1]), "r"(a[2]), "r"(a[3]), "r"(b[0]), "r"(b[1]));
}

__device__ __forceinline__ void cp_async16(void* dst, const void* src, bool full) {
    uint32_t d = (uint32_t)__cvta_generic_to_shared(dst);
    int sz = full ? 16 : 0;
    asm volatile("cp.async.cg.shared.global [%0], [%1], 16, %2;\n"
                 :: "r"(d), "l"(src), "r"(sz));
}

#define A_LD 20   // 16 + 4 pad: banks 20*gid+tig form a permutation of 0..31

template <bool TRANSB, int BN, bool EPI, int ACT>
__global__ __launch_bounds__(256, 2)
void gemm_tf32(const float* __restrict__ A, const float* __restrict__ B,
               float* __restrict__ C, int M, int N, int K,
               const float* __restrict__ attS, const float* __restrict__ attD) {
    constexpr int NF  = BN / 16;
    constexpr int BLD = BN + 8;
    constexpr int BSZ = TRANSB ? BN * A_LD : 16 * BLD;
    __shared__ float As[2][128][A_LD];
    __shared__ float Bs[2][BSZ];

    const int t    = threadIdx.x;
    const int lane = t & 31;
    const int warp = t >> 5;
    const int wm   = warp >> 1;
    const int wn   = warp & 1;
    const int gid  = lane >> 2;
    const int tig  = lane & 3;

    const int mb = blockIdx.y * 128;
    const int nb = blockIdx.x * BN;

    float acc[2][NF][4];
#pragma unroll
    for (int i = 0; i < 2; i++)
#pragma unroll
        for (int j = 0; j < NF; j++)
#pragma unroll
            for (int r = 0; r < 4; r++) acc[i][j][r] = 0.f;

    auto load_tile = [&](int s, int k0) {
#pragma unroll
        for (int h = 0; h < 2; h++) {
            int idx = t + h * 256;
            int row = idx >> 2;
            int kq  = (idx & 3) * 4;
            cp_async16(&As[s][row][kq],
                       A + (size_t)(mb + row) * K + k0 + kq,
                       (mb + row) < M);
        }
        if (!TRANSB) {
#pragma unroll
            for (int h = 0; h < BN / 64; h++) {
                int idx = t + h * 256;
                int kk  = idx / (BN / 4);
                int nn  = (idx % (BN / 4)) * 4;
                cp_async16(&Bs[s][kk * BLD + nn],
                           B + (size_t)(k0 + kk) * N + nb + nn, true);
            }
        } else {
#pragma unroll
            for (int h = 0; h < BN / 64; h++) {
                int idx = t + h * 256;
                int nn  = idx >> 2;
                int kq  = (idx & 3) * 4;
                cp_async16(&Bs[s][nn * A_LD + kq],
                           B + (size_t)(nb + nn) * K + k0 + kq, true);
            }
        }
        asm volatile("cp.async.commit_group;\n" ::: "memory");
    };

    const int KT = K >> 4;
    load_tile(0, 0);

    for (int kt = 0; kt < KT; kt++) {
        const int s = kt & 1;
        if (kt + 1 < KT) {
            load_tile(s ^ 1, (kt + 1) << 4);
            asm volatile("cp.async.wait_group 1;\n" ::: "memory");
        } else {
            asm volatile("cp.async.wait_group 0;\n" ::: "memory");
        }
        __syncthreads();

#pragma unroll
        for (int kc = 0; kc < 16; kc += 8) {
            uint32_t af[2][4], bf[NF][2];
#pragma unroll
            for (int i = 0; i < 2; i++) {
                int row = wm * 32 + i * 16 + gid;
                af[i][0] = f2tf32(As[s][row][kc + tig]);
                af[i][1] = f2tf32(As[s][row + 8][kc + tig]);
                af[i][2] = f2tf32(As[s][row][kc + tig + 4]);
                af[i][3] = f2tf32(As[s][row + 8][kc + tig + 4]);
            }
#pragma unroll
            for (int j = 0; j < NF; j++) {
                int col = wn * (BN / 2) + j * 8 + gid;
                if (!TRANSB) {
                    bf[j][0] = f2tf32(Bs[s][(kc + tig) * BLD + col]);
                    bf[j][1] = f2tf32(Bs[s][(kc + tig + 4) * BLD + col]);
                } else {
                    bf[j][0] = f2tf32(Bs[s][col * A_LD + kc + tig]);
                    bf[j][1] = f2tf32(Bs[s][col * A_LD + kc + tig + 4]);
                }
            }
#pragma unroll
            for (int i = 0; i < 2; i++)
#pragma unroll
                for (int j = 0; j < NF; j++)
                    mma_tf32(acc[i][j], af[i], bf[j]);
        }
        __syncthreads();
    }

    if (ACT == 1) {
#pragma unroll
        for (int i = 0; i < 2; i++)
#pragma unroll
            for (int j = 0; j < NF; j++)
#pragma unroll
                for (int r = 0; r < 4; r++)
                    acc[i][j][r] = acc[i][j][r] > 0.f ? acc[i][j][r] : 0.f;
    }

#pragma unroll
    for (int i = 0; i < 2; i++) {
        int r0 = mb + wm * 32 + i * 16 + gid;
#pragma unroll
        for (int j = 0; j < NF; j++) {
            int c0 = nb + wn * (BN / 2) + j * 8 + tig * 2;
            if (r0 < M)
                *(float2*)(C + (size_t)r0 * N + c0) = make_float2(acc[i][j][0], acc[i][j][1]);
            if (r0 + 8 < M)
                *(float2*)(C + (size_t)(r0 + 8) * N + c0) = make_float2(acc[i][j][2], acc[i][j][3]);
        }
    }

    if (EPI) {
#pragma unroll
        for (int i = 0; i < 2; i++) {
            float ps = 0.f, pd = 0.f, ps8 = 0.f, pd8 = 0.f;
#pragma unroll
            for (int j = 0; j < NF; j++) {
                int c0 = nb + wn * (BN / 2) + j * 8 + tig * 2;
                float sa = __ldg(attS + c0), sb = __ldg(attS + c0 + 1);
                float da = __ldg(attD + c0), db = __ldg(attD + c0 + 1);
                ps  += acc[i][j][0] * sa + acc[i][j][1] * sb;
                pd  += acc[i][j][0] * da + acc[i][j][1] * db;
                ps8 += acc[i][j][2] * sa + acc[i][j][3] * sb;
                pd8 += acc[i][j][2] * da + acc[i][j][3] * db;
            }
#pragma unroll
            for (int o = 1; o <= 2; o <<= 1) {
                ps  += __shfl_xor_sync(0xffffffffu, ps,  o);
                pd  += __shfl_xor_sync(0xffffffffu, pd,  o);
                ps8 += __shfl_xor_sync(0xffffffffu, ps8, o);
                pd8 += __shfl_xor_sync(0xffffffffu, pd8, o);
            }
            if (tig == 0) {
                int r0 = mb + wm * 32 + i * 16 + gid;
                if (r0 < M)     { atomicAdd(&g_asrc[r0], ps);      atomicAdd(&g_adst[r0], pd); }
                if (r0 + 8 < M) { atomicAdd(&g_asrc[r0 + 8], ps8); atomicAdd(&g_adst[r0 + 8], pd8); }
            }
        }
    }
}

// ---------------- launch ----------------
extern "C" void kernel_launch(void* const* d_in, const int* in_sizes, int n_in,
                              void* d_out, int out_size) {
    const float* x        = (const float*)d_in[0];
    const int*   ei       = (const int*)d_in[1];
    const float* W1       = (const float*)d_in[2];
    const float* W2       = (const float*)d_in[3];
    const float* att_src1 = (const float*)d_in[4];
    const float* att_dst1 = (const float*)d_in[5];

    float* latent = (float*)d_out;                               // [N, LAT]
    float* recon  = latent + (size_t)N_NODES * LAT;              // [N, IN_DIM]
    const int* src = ei;
    const int* dst = ei + N_EDGES;

    float *h1, *h1o, *aggL, *h3o;
    cudaGetSymbolAddress((void**)&h1,   g_h1);
    cudaGetSymbolAddress((void**)&h1o,  g_h1o);
    cudaGetSymbolAddress((void**)&aggL, g_aggL);
    cudaGetSymbolAddress((void**)&h3o,  g_h3o);

    const int EB = (N_EDGES + 255) / 256;
    const int NB = (N_NODES + 255) / 256;
    const int WB = (N_NODES * 32 + 255) / 256;   // warp-per-node kernels
    const int MT = (N_NODES + 127) / 128;        // gemm M tiles
    const int SB = (N_NODES + 1023) / 1024;      // scan blocks (49)

    // init (zeroes deg + att-dot accumulators)
    k_zero<<<NB, 256>>>();

    // encoder GAT1 GEMM: h1 = x @ W1 + fused att dots
    gemm_tf32<false, 128, true, 0><<<dim3(HID / 128, MT), 256>>>(
        x, W1, h1, N_NODES, HID, IN_DIM, att_src1, att_dst1);

    // CSR build (3-kernel parallel scan)
    k_count<<<EB, 256>>>(dst);
    k_scan1<<<SB, 1024>>>();
    k_scan2<<<1, 64>>>(SB);
    k_scan3<<<NB, 256>>>();
    k_fill<<<EB, 256>>>(src, dst);

    // encoder edge phase: fused softmax + aggregation (ELU)
    k_smax_agg_elu<<<WB, 256>>>(h1, h1o);

    // encoder GAT2: latent = h1o @ W2
    gemm_tf32<false, 64, false, 0><<<dim3(LAT / 64, MT), 256>>>(
        h1o, W2, latent, N_NODES, LAT, HID, nullptr, nullptr);

    // decoder GAT1 (restructured): aggregate latent, then h3o = relu(aggL @ W2^T)
    k_agg_lat<<<WB, 256>>>(latent, aggL);
    gemm_tf32<true, 128, false, 1><<<dim3(HID / 128, MT), 256>>>(
        aggL, W2, h3o, N_NODES, HID, LAT, nullptr, nullptr);

    // decoder GAT2: recon = h3o @ W1^T
    gemm_tf32<true, 128, false, 0><<<dim3(IN_DIM / 128, MT), 256>>>(
        h3o, W1, recon, N_NODES, IN_DIM, HID, nullptr, nullptr);
}